// round 2
// baseline (speedup 1.0000x reference)
#include <cuda_runtime.h>
#include <cstdint>

#define UNITS   512
#define NBATCH  512
#define DIM     64
#define MTILE   128
#define LD      68            // 64 + 4 pad -> conflict-free fragment LDS
#define WSZ     (DIM * LD)    // 4352 floats per weight matrix
#define XSZ     (MTILE * LD)  // 8704 floats per activation tile
#define NTHREADS 256

// ---------------------------------------------------------------------------
// helpers
// ---------------------------------------------------------------------------
__device__ __forceinline__ uint32_t f2tf32(float x) {
    uint32_t u;
    asm volatile("cvt.rna.tf32.f32 %0, %1;" : "=r"(u) : "f"(x));
    return u;
}

__device__ __forceinline__ void mma_tf32(float* d, const uint32_t* a, const uint32_t* b) {
    asm volatile(
        "mma.sync.aligned.m16n8k8.row.col.f32.tf32.tf32.f32 "
        "{%0,%1,%2,%3}, {%4,%5,%6,%7}, {%8,%9}, {%0,%1,%2,%3};"
        : "+f"(d[0]), "+f"(d[1]), "+f"(d[2]), "+f"(d[3])
        : "r"(a[0]), "r"(a[1]), "r"(a[2]), "r"(a[3]), "r"(b[0]), "r"(b[1]));
}

__device__ __forceinline__ float fast_sigmoid(float v) {
    return 1.f / (1.f + __expf(-v));
}
__device__ __forceinline__ float fast_tanh(float v) {
    return 2.f / (1.f + __expf(-2.f * v)) - 1.f;
}

// One 32x32 warp-tile GEMM over K=64: acc += A(tile) @ W.
// A fragments come from sA (tf32-pre-rounded if CVT==false, rna-converted here
// if CVT==true). B fragments come from sWg (always pre-rounded).
template <bool CVT>
__device__ __forceinline__ void gemm64(const float* __restrict__ sA,
                                       const float* __restrict__ sWg,
                                       float* acc, int g, int t,
                                       int rowBase, int colBase) {
#pragma unroll
    for (int k0 = 0; k0 < DIM; k0 += 8) {
        uint32_t a[2][4], b[4][2];
#pragma unroll
        for (int mi = 0; mi < 2; mi++) {
            const float* ap = sA + (rowBase + mi * 16 + g) * LD + k0 + t;
            float f0 = ap[0];
            float f1 = ap[8 * LD];
            float f2 = ap[4];
            float f3 = ap[8 * LD + 4];
            if (CVT) {
                a[mi][0] = f2tf32(f0); a[mi][1] = f2tf32(f1);
                a[mi][2] = f2tf32(f2); a[mi][3] = f2tf32(f3);
            } else {
                a[mi][0] = __float_as_uint(f0); a[mi][1] = __float_as_uint(f1);
                a[mi][2] = __float_as_uint(f2); a[mi][3] = __float_as_uint(f3);
            }
        }
#pragma unroll
        for (int ni = 0; ni < 4; ni++) {
            const float* bp = sWg + (k0 + t) * LD + colBase + ni * 8 + g;
            b[ni][0] = __float_as_uint(bp[0]);
            b[ni][1] = __float_as_uint(bp[4 * LD]);
        }
#pragma unroll
        for (int mi = 0; mi < 2; mi++)
#pragma unroll
            for (int ni = 0; ni < 4; ni++)
                mma_tf32(acc + (mi * 4 + ni) * 4, a[mi], b[ni]);
    }
}

// ---------------------------------------------------------------------------
// kernel: one CTA per unit; weights resident in smem; 4 batch tiles of 128
// ---------------------------------------------------------------------------
__global__ void __launch_bounds__(NTHREADS, 1)
gru_unitwise_kernel(const float* __restrict__ x,  const float* __restrict__ h,
                    const float* __restrict__ Wir, const float* __restrict__ bir,
                    const float* __restrict__ Whr, const float* __restrict__ bhr,
                    const float* __restrict__ Wiz, const float* __restrict__ biz,
                    const float* __restrict__ Whz, const float* __restrict__ bhz,
                    const float* __restrict__ Win, const float* __restrict__ bin,
                    const float* __restrict__ Whn, const float* __restrict__ bhn,
                    float* __restrict__ out) {
    extern __shared__ float smem[];
    float* sW    = smem;              // 6 * WSZ  (tf32-rounded weights: ir,hr,iz,hz,in,hn)
    float* sX    = sW + 6 * WSZ;      // XSZ      (tf32-rounded x tile)
    float* sH    = sX + XSZ;          // XSZ      (raw fp32 h tile — exact epilogue blend)
    float* sBias = sH + XSZ;          // 4*DIM    (b_r, b_z, b_in, b_hn)

    const int u    = blockIdx.x;
    const int tid  = threadIdx.x;
    const int lane = tid & 31;
    const int wid  = tid >> 5;
    const int g    = lane >> 2;  // groupID
    const int t    = lane & 3;   // thread-in-group
    const int rowBase = (wid & 3) * 32;   // 4 warp rows cover M=128
    const int colBase = (wid >> 2) * 32;  // 2 warp cols cover N=64

    // ---- load 6 weight matrices once (tf32 rna-rounded), padded stride ----
    {
        const float* wsrc[6] = {Wir, Whr, Wiz, Whz, Win, Whn};
        const size_t wOff = (size_t)u * DIM * DIM;
#pragma unroll
        for (int gg = 0; gg < 6; gg++) {
            const float* wp = wsrc[gg] + wOff;
            float* dst = sW + gg * WSZ;
            for (int i = tid; i < DIM * DIM / 4; i += NTHREADS) {
                int r  = i >> 4;
                int c4 = (i & 15) * 4;
                float4 v = *reinterpret_cast<const float4*>(wp + r * DIM + c4);
                float4 o;
                o.x = __uint_as_float(f2tf32(v.x));
                o.y = __uint_as_float(f2tf32(v.y));
                o.z = __uint_as_float(f2tf32(v.z));
                o.w = __uint_as_float(f2tf32(v.w));
                *reinterpret_cast<float4*>(dst + r * LD + c4) = o;
            }
        }
        if (tid < DIM) {
            const size_t bo = (size_t)u * DIM + tid;
            sBias[tid]           = bir[bo] + bhr[bo];
            sBias[DIM + tid]     = biz[bo] + bhz[bo];
            sBias[2 * DIM + tid] = bin[bo];
            sBias[3 * DIM + tid] = bhn[bo];
        }
    }

    for (int tile = 0; tile < NBATCH / MTILE; tile++) {
        const int b0 = tile * MTILE;

        // ---- stage x (rounded) and h (raw) tiles ----
        for (int i = tid; i < MTILE * DIM / 4; i += NTHREADS) {
            int r  = i >> 4;
            int c4 = (i & 15) * 4;
            size_t gaddr = ((size_t)(b0 + r) * UNITS + u) * DIM + c4;
            float4 vx = *reinterpret_cast<const float4*>(x + gaddr);
            float4 ox;
            ox.x = __uint_as_float(f2tf32(vx.x));
            ox.y = __uint_as_float(f2tf32(vx.y));
            ox.z = __uint_as_float(f2tf32(vx.z));
            ox.w = __uint_as_float(f2tf32(vx.w));
            *reinterpret_cast<float4*>(sX + r * LD + c4) = ox;
            float4 vh = *reinterpret_cast<const float4*>(h + gaddr);
            *reinterpret_cast<float4*>(sH + r * LD + c4) = vh;
        }
        __syncthreads();

        // ---- 6 GEMMs into 4 accumulators ----
        float accR[32], accZ[32], accXN[32], accHN[32];
#pragma unroll
        for (int i = 0; i < 32; i++) {
            accR[i] = 0.f; accZ[i] = 0.f; accXN[i] = 0.f; accHN[i] = 0.f;
        }
        gemm64<false>(sX, sW + 0 * WSZ, accR,  g, t, rowBase, colBase);  // x@Wir
        gemm64<true >(sH, sW + 1 * WSZ, accR,  g, t, rowBase, colBase);  // h@Whr
        gemm64<false>(sX, sW + 2 * WSZ, accZ,  g, t, rowBase, colBase);  // x@Wiz
        gemm64<true >(sH, sW + 3 * WSZ, accZ,  g, t, rowBase, colBase);  // h@Whz
        gemm64<false>(sX, sW + 4 * WSZ, accXN, g, t, rowBase, colBase);  // x@Win
        gemm64<true >(sH, sW + 5 * WSZ, accHN, g, t, rowBase, colBase);  // h@Whn

        // ---- fused GRU epilogue, float2 stores ----
#pragma unroll
        for (int mi = 0; mi < 2; mi++) {
#pragma unroll
            for (int ni = 0; ni < 4; ni++) {
                const int base = (mi * 4 + ni) * 4;
                const int col  = colBase + ni * 8 + 2 * t;
#pragma unroll
                for (int half = 0; half < 2; half++) {
                    const int row = rowBase + mi * 16 + g + half * 8;
                    float2 res;
                    float* rp = &res.x;
#pragma unroll
                    for (int cc = 0; cc < 2; cc++) {
                        const int idx = base + half * 2 + cc;
                        const int o   = col + cc;
                        float r_ = fast_sigmoid(accR[idx] + sBias[o]);
                        float z_ = fast_sigmoid(accZ[idx] + sBias[DIM + o]);
                        float n_ = fast_tanh(accXN[idx] + sBias[2 * DIM + o] +
                                             r_ * (accHN[idx] + sBias[3 * DIM + o]));
                        float hv = sH[row * LD + o];
                        rp[cc] = (1.f - z_) * n_ + z_ * hv;
                    }
                    size_t ga = ((size_t)(b0 + row) * UNITS + u) * DIM + col;
                    *reinterpret_cast<float2*>(out + ga) = res;
                }
            }
        }
        __syncthreads();  // protect sX/sH before next tile's staging
    }
}

// ---------------------------------------------------------------------------
// launch
// ---------------------------------------------------------------------------
extern "C" void kernel_launch(void* const* d_in, const int* in_sizes, int n_in,
                              void* d_out, int out_size) {
    (void)in_sizes; (void)n_in; (void)out_size;
    const float* x   = (const float*)d_in[0];
    const float* h   = (const float*)d_in[1];
    const float* Wir = (const float*)d_in[2];
    const float* bir = (const float*)d_in[3];
    const float* Whr = (const float*)d_in[4];
    const float* bhr = (const float*)d_in[5];
    const float* Wiz = (const float*)d_in[6];
    const float* biz = (const float*)d_in[7];
    const float* Whz = (const float*)d_in[8];
    const float* bhz = (const float*)d_in[9];
    const float* Win = (const float*)d_in[10];
    const float* bin = (const float*)d_in[11];
    const float* Whn = (const float*)d_in[12];
    const float* bhn = (const float*)d_in[13];
    float* out = (float*)d_out;

    const size_t smemBytes = (size_t)(6 * WSZ + 2 * XSZ + 4 * DIM) * sizeof(float);
    cudaFuncSetAttribute(gru_unitwise_kernel,
                         cudaFuncAttributeMaxDynamicSharedMemorySize, (int)smemBytes);

    gru_unitwise_kernel<<<UNITS, NTHREADS, smemBytes>>>(
        x, h, Wir, bir, Whr, bhr, Wiz, biz, Whz, bhz, Win, bin, Whn, bhn, out);
}